// round 11
// baseline (speedup 1.0000x reference)
#include <cuda_runtime.h>
#include <cstdint>

#define NVEH 16384
#define NT   256
#define H    20

#define VPC   64                 // vehicles per CTA
#define TPC   160                // 4 grps x 40 (20 units x 2 parities)
#define NCTA  (NVEH / VPC)       // 256
#define PPG   8                  // pairs per grp (16 vehicles)
#define NPAIR 32                 // pairs per CTA
#define RS    24                 // ull per h row (20 used + 4 pad)

typedef unsigned long long ull;

// gWp[lane*48 + slot], lane = u*2+par. Chains: A = par? f : i, B = par? o : g.
//   slot 0..22 : chain A rows (x0,x1,x2, U0..U19), slot 23: A bias
//   slot 24..46: chain B rows,                     slot 47: B bias
// Weights duplicated into both f32x2 lanes; sigmoid gates prescaled x0.5.
__device__ float2 gWp[40 * 48];
__device__ float  gWdv[24];      // Wd[0..19], bd at [20]

// ---------- packed f32x2 helpers ----------
__device__ __forceinline__ void ffma2(ull& d, ull a, ull b) {
    asm("fma.rn.f32x2 %0, %1, %2, %0;" : "+l"(d) : "l"(a), "l"(b));
}
__device__ __forceinline__ ull mul2(ull a, ull b) {
    ull r; asm("mul.rn.f32x2 %0, %1, %2;" : "=l"(r) : "l"(a), "l"(b)); return r;
}
__device__ __forceinline__ ull add2(ull a, ull b) {
    ull r; asm("add.rn.f32x2 %0, %1, %2;" : "=l"(r) : "l"(a), "l"(b)); return r;
}
__device__ __forceinline__ ull pack2(float lo, float hi) {
    ull r; asm("mov.b64 %0, {%1, %2};" : "=l"(r) : "f"(lo), "f"(hi)); return r;
}
__device__ __forceinline__ float lo32(ull v) {
    float f; asm("{ .reg .b32 hi; mov.b64 {%0, hi}, %1; }" : "=f"(f) : "l"(v)); return f;
}
__device__ __forceinline__ float hi32(ull v) {
    float f; asm("{ .reg .b32 lo; mov.b64 {lo, %0}, %1; }" : "=f"(f) : "l"(v)); return f;
}
__device__ __forceinline__ float fast_tanh(float x) {
    float y; asm("tanh.approx.f32 %0, %1;" : "=f"(y) : "f"(x)); return y;
}

// ---------- repack ----------
__global__ void repack_kernel(const float* __restrict__ W,
                              const float* __restrict__ U,
                              const float* __restrict__ b,
                              const float* __restrict__ Wd,
                              const float* __restrict__ bd)
{
    int i = blockIdx.x * blockDim.x + threadIdx.x;
    if (i < 40 * 48) {
        int lane = i / 48, s = i % 48;
        int u = lane >> 1, par = lane & 1;
        int chain = s / 24, loc = s % 24;
        int gidx = chain == 0 ? (par ? 1 : 0) : (par ? 3 : 2);
        int col = gidx * 20 + u;
        float sc = (gidx == 2) ? 1.0f : 0.5f;
        float w;
        if (loc < 3)       w = W[loc * 80 + col];
        else if (loc < 23) w = U[(loc - 3) * 80 + col];
        else               w = b[col];
        w *= sc;
        gWp[i] = make_float2(w, w);
    }
    if (i < 20)  gWdv[i]  = Wd[i];
    if (i == 20) gWdv[20] = bd[0];
}

__global__ __launch_bounds__(TPC, 2)
void rnncf_kernel(const float* __restrict__ lead_inputs,  // (NVEH, NT, 2)
                  const float* __restrict__ init_state,   // (NVEH, 2)
                  const float* __restrict__ h0,           // (NVEH, H)
                  const float* __restrict__ c0,           // (NVEH, H)
                  float* __restrict__ out,
                  int out_size)
{
    __shared__ ull hb[2][NPAIR * RS];                 // h pairs, double buffered
    __shared__ __align__(16) float sx[2][3][VPC];     // x rows: [buf][slot][veh]
    __shared__ float swd[24];                         // Wd + bd for drivers

    const int tid = threadIdx.x;
    const int grp = tid / 40;
    const int r   = tid % 40;
    const int u   = r >> 1;
    const int par = r & 1;
    const int pb  = grp * PPG;
    const int vcta = blockIdx.x * VPC;

    // ---- weights into registers ----
    ull wA[23], wB[23], bA, bB;
    {
        const ull* blk = reinterpret_cast<const ull*>(gWp) + r * 48;
#pragma unroll
        for (int k = 0; k < 23; ++k) { wA[k] = blk[k]; wB[k] = blk[24 + k]; }
        bA = blk[23]; bB = blk[47];
    }
    if (tid < 24) swd[tid] = gWdv[tid];

    // ---- init state ----
    ull cc[PPG];        // c pairs, live on par1 only
#pragma unroll
    for (int p = 0; p < PPG; ++p) {
        const int vA = vcta + 2 * (pb + p);
        if (par) cc[p] = pack2(c0[vA * H + u], c0[(vA + 1) * H + u]);
        else     hb[0][(pb + p) * RS + u] =
                     pack2(h0[vA * H + u], h0[(vA + 1) * H + u]);
    }

    // driver state (threads 0..63 ~ vehicles)
    float pos = 0.f, spd = 0.f;
    const float2* mylead = nullptr;
    if (tid < VPC) {
        const int gv = vcta + tid;
        pos = init_state[2 * gv];
        spd = init_state[2 * gv + 1];
        mylead = reinterpret_cast<const float2*>(lead_inputs) + (size_t)gv * NT;
        float2 l0 = mylead[0];
        sx[0][0][tid] = (l0.x - pos) * 0.01f;
        sx[0][1][tid] = spd * 0.025f;
        sx[0][2][tid] = l0.y * 0.025f;
    }
    __syncthreads();

    const bool extras = (out_size >= NT * NVEH + NVEH + 2 * NVEH * H);

#pragma unroll 1
    for (int t = 0; t < NT; ++t) {
        const int cur = t & 1, nxb = cur ^ 1;
        const ull* rbh = hb[cur];
        ull*       wbh = hb[nxb];

        float2 nl = make_float2(0.f, 0.f);
        if (tid < VPC) {
            int tn = (t + 1 < NT) ? (t + 1) : (NT - 1);
            nl = mylead[tn];
        }

        // ---- GEMM + gates: blocks of 2 pairs, 8-way interleaved accumulators ----
#pragma unroll 1
        for (int pblk = 0; pblk < PPG; pblk += 2) {
            const int gp0 = pb + pblk, gp1 = gp0 + 1;
            const ulonglong2* rp0 =
                reinterpret_cast<const ulonglong2*>(rbh + gp0 * RS);
            const ulonglong2* rp1 =
                reinterpret_cast<const ulonglong2*>(rbh + gp1 * RS);

            ull x00 = *reinterpret_cast<const ull*>(&sx[cur][0][2 * gp0]);
            ull x01 = *reinterpret_cast<const ull*>(&sx[cur][1][2 * gp0]);
            ull x02 = *reinterpret_cast<const ull*>(&sx[cur][2][2 * gp0]);
            ull x10 = *reinterpret_cast<const ull*>(&sx[cur][0][2 * gp1]);
            ull x11 = *reinterpret_cast<const ull*>(&sx[cur][1][2 * gp1]);
            ull x12 = *reinterpret_cast<const ull*>(&sx[cur][2][2 * gp1]);

            // 8 independent accumulator streams (2 pairs x 2 chains x split)
            ull aA0 = bA, aB0 = bB, aA1 = bA, aB1 = bB;      // "a" halves
            ull cA0 = 0,  cB0 = 0,  cA1 = 0,  cB1 = 0;       // "b" halves
            // x rows spread across halves
            ffma2(aA0, wA[0], x00); ffma2(aB0, wB[0], x00);
            ffma2(aA1, wA[0], x10); ffma2(aB1, wB[0], x10);
            ffma2(cA0, wA[1], x01); ffma2(cB0, wB[1], x01);
            ffma2(cA1, wA[1], x11); ffma2(cB1, wB[1], x11);
            ffma2(aA0, wA[2], x02); ffma2(aB0, wB[2], x02);
            ffma2(aA1, wA[2], x12); ffma2(aB1, wB[2], x12);

#pragma unroll
            for (int j = 0; j < 10; ++j) {
                ulonglong2 h0v = rp0[j];
                ulonglong2 h1v = rp1[j];
                ffma2(aA0, wA[3 + 2 * j], h0v.x);
                ffma2(aA1, wA[3 + 2 * j], h1v.x);
                ffma2(aB0, wB[3 + 2 * j], h0v.x);
                ffma2(aB1, wB[3 + 2 * j], h1v.x);
                ffma2(cA0, wA[4 + 2 * j], h0v.y);
                ffma2(cA1, wA[4 + 2 * j], h1v.y);
                ffma2(cB0, wB[4 + 2 * j], h0v.y);
                ffma2(cB1, wB[4 + 2 * j], h1v.y);
            }
            ull zA0 = add2(aA0, cA0), zB0 = add2(aB0, cB0);
            ull zA1 = add2(aA1, cA1), zB1 = add2(aB1, cB1);

            // interleaved activation tails for both pairs
            float tA00 = fast_tanh(lo32(zA0)), tA01 = fast_tanh(hi32(zA0));
            float tA10 = fast_tanh(lo32(zA1)), tA11 = fast_tanh(hi32(zA1));
            float tB00 = fast_tanh(lo32(zB0)), tB01 = fast_tanh(hi32(zB0));
            float tB10 = fast_tanh(lo32(zB1)), tB11 = fast_tanh(hi32(zB1));

            ull gA0 = pack2(fmaf(0.5f, tA00, 0.5f), fmaf(0.5f, tA01, 0.5f));
            ull gA1 = pack2(fmaf(0.5f, tA10, 0.5f), fmaf(0.5f, tA11, 0.5f));
            ull gB0 = par ? pack2(fmaf(0.5f, tB00, 0.5f), fmaf(0.5f, tB01, 0.5f))
                          : pack2(tB00, tB01);
            ull gB1 = par ? pack2(fmaf(0.5f, tB10, 0.5f), fmaf(0.5f, tB11, 0.5f))
                          : pack2(tB10, tB11);

            ull m0 = par ? gA0 : mul2(gA0, gB0);   // par0 sends si*tg
            ull m1 = par ? gA1 : mul2(gA1, gB1);
            ull got0 = __shfl_xor_sync(0xffffffffu, m0, 1);
            ull got1 = __shfl_xor_sync(0xffffffffu, m1, 1);
            if (par) {
                ull cn0 = got0; ffma2(cn0, gA0, cc[pblk]);
                ull cn1 = got1; ffma2(cn1, gA1, cc[pblk + 1]);
                cc[pblk] = cn0; cc[pblk + 1] = cn1;
                float u00 = fast_tanh(lo32(cn0)), u01 = fast_tanh(hi32(cn0));
                float u10 = fast_tanh(lo32(cn1)), u11 = fast_tanh(hi32(cn1));
                wbh[gp0 * RS + u] = mul2(gB0, pack2(u00, u01));
                wbh[gp1 * RS + u] = mul2(gB1, pack2(u10, u11));
            }
        }
        __syncthreads();

        // ---- driver phase: Wd dot on h(t+1), pos/spd, out, x(t+1) ----
        if (tid < VPC) {
            const int lane = tid & 1;
            const float4* p4 =
                reinterpret_cast<const float4*>(wbh + (tid >> 1) * RS);
            float s0 = swd[20], s1 = 0.f;
#pragma unroll
            for (int j = 0; j < 10; ++j) {
                float4 f = p4[j];
                float vlo = lane ? f.y : f.x;    // h[2j]
                float vhi = lane ? f.w : f.z;    // h[2j+1]
                s0 = fmaf(vlo, swd[2 * j], s0);
                s1 = fmaf(vhi, swd[2 * j + 1], s1);
            }
            float a = fmaf(7.0f, s0 + s1, -4.0f);
            spd = fmaf(0.1f, a, spd);
            pos = fmaf(0.1f, a, pos);
            out[(size_t)t * NVEH + vcta + tid] = pos;
            sx[nxb][0][tid] = (nl.x - pos) * 0.01f;
            sx[nxb][1][tid] = spd * 0.025f;
            sx[nxb][2][tid] = nl.y * 0.025f;
        }
        __syncthreads();
    }

    // ---- extras ----
    if (extras) {
        if (tid < VPC)
            out[(size_t)NT * NVEH + vcta + tid] = spd;
        float* hout  = out + (size_t)NT * NVEH + NVEH;
        float* cout2 = hout + (size_t)NVEH * H;
        const ull* fb = hb[NT & 1];              // h(NT): NT even -> hb[0]
#pragma unroll
        for (int p = 0; p < PPG; ++p) {
            const int vA = vcta + 2 * (pb + p);
            if (par) {
                cout2[vA * H + u]       = lo32(cc[p]);
                cout2[(vA + 1) * H + u] = hi32(cc[p]);
            } else {
                ull hv = fb[(pb + p) * RS + u];
                hout[vA * H + u]        = lo32(hv);
                hout[(vA + 1) * H + u]  = hi32(hv);
            }
        }
    }
}

extern "C" void kernel_launch(void* const* d_in, const int* in_sizes, int n_in,
                              void* d_out, int out_size) {
    const float* lead_inputs = (const float*)d_in[0];
    const float* init_state  = (const float*)d_in[1];
    const float* h0          = (const float*)d_in[2];
    const float* c0          = (const float*)d_in[3];
    const float* W           = (const float*)d_in[4];
    const float* U           = (const float*)d_in[5];
    const float* b           = (const float*)d_in[6];
    const float* Wd          = (const float*)d_in[7];
    const float* bd          = (const float*)d_in[8];

    repack_kernel<<<2, 1024>>>(W, U, b, Wd, bd);
    rnncf_kernel<<<NCTA, TPC>>>(lead_inputs, init_state, h0, c0,
                                (float*)d_out, out_size);
}

// round 12
// speedup vs baseline: 1.1243x; 1.1243x over previous
#include <cuda_runtime.h>
#include <cstdint>

#define NVEH 16384
#define NT   256
#define H    20

#define VPC  64                 // vehicles per CTA
#define TPC  160                // 8 grps x 20 unit-threads
#define NCTA (NVEH / VPC)       // 256
#define VPT  8                  // vehicles per thread
#define RSU  26                 // ull stride per vehicle row (24 used + 2 pad)

typedef unsigned long long ull;

// Per-unit packed weights (identical to the 621us kernel):
//  slot 0..23: IF pairs (0..2 = W rows, 3 = zero pad, 4..23 = U rows)
//  slot 24..47: GO pairs, slot 48 = bias IF, 49 = bias GO
__device__ float2 gWt[20 * 50];
__device__ float  gWd[24];      // Wd[0..19], bd at [20]

// ---------- packed f32x2 helpers ----------
__device__ __forceinline__ void ffma2(ull& d, ull a, ull b) {
    asm("fma.rn.f32x2 %0, %1, %2, %0;" : "+l"(d) : "l"(a), "l"(b));
}
__device__ __forceinline__ ull pack2(float lo, float hi) {
    ull r; asm("mov.b64 %0, {%1, %2};" : "=l"(r) : "f"(lo), "f"(hi)); return r;
}
__device__ __forceinline__ float lo32(ull v) {
    float f; asm("{ .reg .b32 hi; mov.b64 {%0, hi}, %1; }" : "=f"(f) : "l"(v)); return f;
}
__device__ __forceinline__ float hi32(ull v) {
    float f; asm("{ .reg .b32 lo; mov.b64 {lo, %0}, %1; }" : "=f"(f) : "l"(v)); return f;
}
__device__ __forceinline__ float fast_tanh(float x) {
    float y; asm("tanh.approx.f32 %0, %1;" : "=f"(y) : "f"(x)); return y;
}
__device__ __forceinline__ float fast_sig(float x) {
    return fmaf(0.5f, fast_tanh(0.5f * x), 0.5f);
}

// ---------- repack (identical to 621us kernel) ----------
__global__ void repack_kernel(const float* __restrict__ W,
                              const float* __restrict__ U,
                              const float* __restrict__ b,
                              const float* __restrict__ Wd,
                              const float* __restrict__ bd)
{
    int i = blockIdx.x * blockDim.x + threadIdx.x;
    if (i < 20 * 50) {
        int u = i / 50, s = i % 50;
        float a0 = 0.f, a1 = 0.f;
        if (s < 24) {                       // IF pair, slot s
            if (s < 3)       { a0 = W[s * 80 + u];        a1 = W[s * 80 + 20 + u]; }
            else if (s >= 4) { a0 = U[(s - 4) * 80 + u];  a1 = U[(s - 4) * 80 + 20 + u]; }
        } else if (s < 48) {                // GO pair, slot s-24
            int k = s - 24;
            if (k < 3)       { a0 = W[k * 80 + 40 + u];       a1 = W[k * 80 + 60 + u]; }
            else if (k >= 4) { a0 = U[(k - 4) * 80 + 40 + u]; a1 = U[(k - 4) * 80 + 60 + u]; }
        } else if (s == 48)  { a0 = b[u];      a1 = b[20 + u]; }
        else                 { a0 = b[40 + u]; a1 = b[60 + u]; }
        gWt[i] = make_float2(a0, a1);
    }
    if (i < 20)  gWd[i]  = Wd[i];
    if (i == 20) gWd[20] = bd[0];
}

__global__ __launch_bounds__(TPC, 2)
void rnncf_kernel(const float* __restrict__ lead_inputs,  // (NVEH, NT, 2)
                  const float* __restrict__ init_state,   // (NVEH, 2)
                  const float* __restrict__ h0,           // (NVEH, H)
                  const float* __restrict__ c0,           // (NVEH, H)
                  float* __restrict__ out,
                  int out_size)
{
    // Double-buffered DUPLICATED activation rows (ull = (v,v) f32 pair):
    // slot 0..2 = x dup, 3 = zero pad, 4+j = h[j] dup. Stride RSU=26 ull.
    __shared__ ull xh[2][VPC * RSU];    // 2 * 64 * 26 * 8B = 26.6 KB

    const int tid = threadIdx.x;
    const int u   = tid % 20;          // unit owned by this thread
    const int grp = tid / 20;          // vehicle group (0..7)
    const int vb  = grp * VPT;

    // ---- this unit's weights into registers (whole sim) ----
    ull wIF[24], wGO[24], bIF, bGO;
    {
        const ull* tb = reinterpret_cast<const ull*>(gWt) + u * 50;
#pragma unroll
        for (int k = 0; k < 24; ++k) { wIF[k] = tb[k]; wGO[k] = tb[24 + k]; }
        bIF = tb[48]; bGO = tb[49];
    }

    // zero the pad slot (slot 3) of every row in both buffers
    for (int i = tid; i < VPC; i += TPC) {
        xh[0][i * RSU + 3] = 0ull;
        xh[1][i * RSU + 3] = 0ull;
    }

    // ---- init state ----
    float cc[VPT];
#pragma unroll
    for (int v = 0; v < VPT; ++v) {
        int gveh = blockIdx.x * VPC + vb + v;
        cc[v] = c0[gveh * H + u];
        float hv = h0[gveh * H + u];
        xh[0][(vb + v) * RSU + 4 + u] = pack2(hv, hv);
    }

    // driver-only state (threads 0..63)
    float pos = 0.f, spd = 0.f, bdv = 0.f;
    float wdr[20];
    const float2* mylead = nullptr;
    if (tid < VPC) {
        int gveh = blockIdx.x * VPC + tid;
        pos = init_state[2 * gveh];
        spd = init_state[2 * gveh + 1];
        mylead = reinterpret_cast<const float2*>(lead_inputs) + (size_t)gveh * NT;
        float2 l0 = mylead[0];
        float x0 = (l0.x - pos) * 0.01f;
        float x1 = spd * 0.025f;
        float x2 = l0.y * 0.025f;
        xh[0][tid * RSU + 0] = pack2(x0, x0);
        xh[0][tid * RSU + 1] = pack2(x1, x1);
        xh[0][tid * RSU + 2] = pack2(x2, x2);
#pragma unroll
        for (int j = 0; j < 20; ++j) wdr[j] = gWd[j];
        bdv = gWd[20];
    }
    __syncthreads();

    const bool write_extras = (out_size >= NT * NVEH + NVEH + 2 * NVEH * H);
    float* outbase = out + blockIdx.x * VPC + tid;

#pragma unroll 1
    for (int t = 0; t < NT; ++t) {
        const ull* rb = xh[t & 1];
        ull*       wb = xh[(t + 1) & 1];

        // driver prefetch of lead[t+1]
        float2 nl = make_float2(0.f, 0.f);
        if (tid < VPC) {
            int tn = (t + 1 < NT) ? (t + 1) : (NT - 1);
            nl = mylead[tn];
        }

        // ---- GEMM + gates: zero-MOV inner loop (dup'd operands from smem) ----
#pragma unroll 2
        for (int v = 0; v < VPT; ++v) {
            const ulonglong2* row =
                reinterpret_cast<const ulonglong2*>(rb + (vb + v) * RSU);
            ull ai = bIF, ag = bGO;
#pragma unroll
            for (int j = 0; j < 12; ++j) {
                ulonglong2 m = row[j];   // two dup'd multipliers
                ffma2(ai, wIF[2 * j],     m.x);
                ffma2(ag, wGO[2 * j],     m.x);
                ffma2(ai, wIF[2 * j + 1], m.y);
                ffma2(ag, wGO[2 * j + 1], m.y);
            }
            float si = fast_sig(lo32(ai));      // sig(i)
            float sf = fast_sig(hi32(ai));      // sig(f)
            float tg = fast_tanh(lo32(ag));     // tanh(g)
            float so = fast_sig(hi32(ag));      // sig(o)
            float cn = fmaf(sf, cc[v], si * tg);
            cc[v] = cn;
            float hn = so * fast_tanh(cn);
            wb[(vb + v) * RSU + 4 + u] = pack2(hn, hn);   // h(t+1) dup'd
        }
        __syncthreads();

        // ---- driver phase: Wd dot on h(t+1), pos/spd, out, x(t+1) ----
        if (tid < VPC) {
            const float* hrow =
                reinterpret_cast<const float*>(wb + tid * RSU) + 8;  // h dup floats
            float s0 = bdv, s1 = 0.f;
#pragma unroll
            for (int j = 0; j < 10; ++j) {
                float4 f = reinterpret_cast<const float4*>(hrow)[j]; // (h2j,h2j,h2j+1,h2j+1)
                s0 = fmaf(f.x, wdr[2 * j],     s0);
                s1 = fmaf(f.z, wdr[2 * j + 1], s1);
            }
            float a = fmaf(7.0f, s0 + s1, -4.0f);   // (MAXA-MINA)*out + MINA
            spd = fmaf(0.1f, a, spd);
            pos = fmaf(0.1f, a, pos);
            outbase[(size_t)t * NVEH] = pos;
            float x0 = (nl.x - pos) * 0.01f;
            float x1 = spd * 0.025f;
            float x2 = nl.y * 0.025f;
            wb[tid * RSU + 0] = pack2(x0, x0);
            wb[tid * RSU + 1] = pack2(x1, x1);
            wb[tid * RSU + 2] = pack2(x2, x2);
        }
        __syncthreads();
    }

    if (write_extras) {
        if (tid < VPC)
            out[(size_t)NT * NVEH + blockIdx.x * VPC + tid] = spd;
        float* hout = out + (size_t)NT * NVEH + NVEH;
        float* cout = hout + (size_t)NVEH * H;
        const ull* fb = xh[NT & 1];   // h(256) lives in buf[0]
#pragma unroll
        for (int v = 0; v < VPT; ++v) {
            int gveh = blockIdx.x * VPC + vb + v;
            hout[gveh * H + u] = lo32(fb[(vb + v) * RSU + 4 + u]);
            cout[gveh * H + u] = cc[v];
        }
    }
}

extern "C" void kernel_launch(void* const* d_in, const int* in_sizes, int n_in,
                              void* d_out, int out_size) {
    const float* lead_inputs = (const float*)d_in[0];
    const float* init_state  = (const float*)d_in[1];
    const float* h0          = (const float*)d_in[2];
    const float* c0          = (const float*)d_in[3];
    const float* W           = (const float*)d_in[4];
    const float* U           = (const float*)d_in[5];
    const float* b           = (const float*)d_in[6];
    const float* Wd          = (const float*)d_in[7];
    const float* bd          = (const float*)d_in[8];

    repack_kernel<<<1, 1024>>>(W, U, b, Wd, bd);
    rnncf_kernel<<<NCTA, TPC>>>(lead_inputs, init_state, h0, c0,
                                (float*)d_out, out_size);
}

// round 13
// speedup vs baseline: 1.2557x; 1.1169x over previous
#include <cuda_runtime.h>
#include <cstdint>

#define NVEH 16384
#define NT   256
#define H    20

#define VPC  32                 // vehicles per CTA
#define TPC  160                // 8 grps x 20 unit-threads
#define NCTA (NVEH / VPC)       // 512
#define VPT  4                  // vehicles per thread  (halved: doubles warp count)
#define RSF  28                 // float stride per vehicle row (24 used + 4 pad)

typedef unsigned long long ull;

// Per-unit packed weights:
//  slot 0..19 : IF pairs for U rows, 20..22: W rows, 23: zero pad
//  slot 24..47: GO pairs same order, 48 = bias IF, 49 = bias GO
__device__ float2 gWt[20 * 50];
__device__ float  gWd[24];      // Wd[0..19], bd at [20]

// ---------- packed f32x2 helpers (sm_103a) ----------
__device__ __forceinline__ void ffma2(ull& d, ull a, ull b) {
    asm("fma.rn.f32x2 %0, %1, %2, %0;" : "+l"(d) : "l"(a), "l"(b));
}
__device__ __forceinline__ ull dup2(float x) {
    ull r; asm("mov.b64 %0, {%1, %1};" : "=l"(r) : "f"(x)); return r;
}
__device__ __forceinline__ float lo32(ull v) {
    float f; asm("{ .reg .b32 hi; mov.b64 {%0, hi}, %1; }" : "=f"(f) : "l"(v)); return f;
}
__device__ __forceinline__ float hi32(ull v) {
    float f; asm("{ .reg .b32 lo; mov.b64 {lo, %0}, %1; }" : "=f"(f) : "l"(v)); return f;
}
__device__ __forceinline__ float fast_tanh(float x) {
    float y; asm("tanh.approx.f32 %0, %1;" : "=f"(y) : "f"(x)); return y;
}
__device__ __forceinline__ float fast_sig(float x) {
    return fmaf(0.5f, fast_tanh(0.5f * x), 0.5f);
}

// ---------- repack ----------
__global__ void repack_kernel(const float* __restrict__ W,
                              const float* __restrict__ U,
                              const float* __restrict__ b,
                              const float* __restrict__ Wd,
                              const float* __restrict__ bd)
{
    int i = blockIdx.x * blockDim.x + threadIdx.x;
    if (i < 20 * 50) {
        int u = i / 50, s = i % 50;
        float a0 = 0.f, a1 = 0.f;
        if (s < 24) {                       // IF pair, slot s
            if (s < 20)      { a0 = U[s * 80 + u];         a1 = U[s * 80 + 20 + u]; }
            else if (s < 23) { a0 = W[(s - 20) * 80 + u];  a1 = W[(s - 20) * 80 + 20 + u]; }
            // s == 23 stays zero (pad)
        } else if (s < 48) {                // GO pair
            int k = s - 24;
            if (k < 20)      { a0 = U[k * 80 + 40 + u];        a1 = U[k * 80 + 60 + u]; }
            else if (k < 23) { a0 = W[(k - 20) * 80 + 40 + u]; a1 = W[(k - 20) * 80 + 60 + u]; }
        } else if (s == 48)  { a0 = b[u];      a1 = b[20 + u]; }
        else                 { a0 = b[40 + u]; a1 = b[60 + u]; }
        gWt[i] = make_float2(a0, a1);
    }
    if (i < 20)  gWd[i]  = Wd[i];
    if (i == 20) gWd[20] = bd[0];
}

__global__ __launch_bounds__(TPC, 3)
void rnncf_kernel(const float* __restrict__ lead_inputs,  // (NVEH, NT, 2)
                  const float* __restrict__ init_state,   // (NVEH, 2)
                  const float* __restrict__ h0,           // (NVEH, H)
                  const float* __restrict__ c0,           // (NVEH, H)
                  float* __restrict__ out,
                  int out_size)
{
    // Double-buffered rows: slots 0..19 = h (16B-aligned), 20..22 = x, 23 = 0 pad.
    __shared__ float xh[2][VPC * RSF];     // 2 * 32 * 28 * 4B = 7 KB
    __shared__ float swd[24];              // Wd + bd (driver phase)

    const int tid = threadIdx.x;
    const int u   = tid % 20;
    const int grp = tid / 20;
    const int vb  = grp * VPT;

    // ---- this unit's weights into registers (whole sim) ----
    ull wIF[24], wGO[24], bIF, bGO;
    {
        const ull* tb = reinterpret_cast<const ull*>(gWt) + u * 50;
#pragma unroll
        for (int k = 0; k < 24; ++k) { wIF[k] = tb[k]; wGO[k] = tb[24 + k]; }
        bIF = tb[48]; bGO = tb[49];
    }
    if (tid < 24) swd[tid] = gWd[tid];

    // zero the pad slot (23) of every row in both buffers
    for (int i = tid; i < VPC; i += TPC) {
        xh[0][i * RSF + 23] = 0.f;
        xh[1][i * RSF + 23] = 0.f;
    }

    // ---- init state ----
    float cc[VPT];
#pragma unroll
    for (int v = 0; v < VPT; ++v) {
        int gveh = blockIdx.x * VPC + vb + v;
        cc[v] = c0[gveh * H + u];
        xh[0][(vb + v) * RSF + u] = h0[gveh * H + u];
    }

    // driver-only state (threads 0..31)
    float pos = 0.f, spd = 0.f;
    const float2* mylead = nullptr;
    if (tid < VPC) {
        int gveh = blockIdx.x * VPC + tid;
        pos = init_state[2 * gveh];
        spd = init_state[2 * gveh + 1];
        mylead = reinterpret_cast<const float2*>(lead_inputs) + (size_t)gveh * NT;
        float2 l0 = mylead[0];
        xh[0][tid * RSF + 20] = (l0.x - pos) * 0.01f;
        xh[0][tid * RSF + 21] = spd * 0.025f;
        xh[0][tid * RSF + 22] = l0.y * 0.025f;
    }
    __syncthreads();

    const bool write_extras = (out_size >= NT * NVEH + NVEH + 2 * NVEH * H);
    float* outbase = out + blockIdx.x * VPC + tid;

#pragma unroll 1
    for (int t = 0; t < NT; ++t) {
        const float* rb = xh[t & 1];
        float*       wb = xh[(t + 1) & 1];

        // driver prefetch of lead[t+1]
        float2 nl = make_float2(0.f, 0.f);
        if (tid < VPC) {
            int tn = (t + 1 < NT) ? (t + 1) : (NT - 1);
            nl = mylead[tn];
        }

        // ---- GEMM + gates for this thread's 4 vehicles ----
#pragma unroll 2
        for (int v = 0; v < VPT; ++v) {
            const float4* row =
                reinterpret_cast<const float4*>(rb + (vb + v) * RSF);
            float4 r0 = row[0];
            float4 r1 = row[1];
            float4 r2 = row[2];
            float4 r3 = row[3];
            float4 r4 = row[4];
            float4 r5 = row[5];   // (x0, x1, x2, 0-pad)

            ull ai = bIF, ag = bGO;
#define KK(kk, val) { ull md = dup2(val); ffma2(ai, wIF[kk], md); ffma2(ag, wGO[kk], md); }
            KK(0,  r0.x) KK(1,  r0.y) KK(2,  r0.z) KK(3,  r0.w)
            KK(4,  r1.x) KK(5,  r1.y) KK(6,  r1.z) KK(7,  r1.w)
            KK(8,  r2.x) KK(9,  r2.y) KK(10, r2.z) KK(11, r2.w)
            KK(12, r3.x) KK(13, r3.y) KK(14, r3.z) KK(15, r3.w)
            KK(16, r4.x) KK(17, r4.y) KK(18, r4.z) KK(19, r4.w)
            KK(20, r5.x) KK(21, r5.y) KK(22, r5.z)
#undef KK

            float si = fast_sig(lo32(ai));      // sig(i)
            float sf = fast_sig(hi32(ai));      // sig(f)
            float tg = fast_tanh(lo32(ag));     // tanh(g)
            float so = fast_sig(hi32(ag));      // sig(o)
            float cn = fmaf(sf, cc[v], si * tg);
            cc[v] = cn;
            wb[(vb + v) * RSF + u] = so * fast_tanh(cn);   // h(t+1)
        }
        __syncthreads();

        // ---- driver phase: Wd dot on h(t+1), pos/spd, out, x(t+1) ----
        if (tid < VPC) {
            const float4* hrow =
                reinterpret_cast<const float4*>(wb + tid * RSF);
            float s0 = swd[20], s1 = 0.f, s2 = 0.f, s3 = 0.f;
#pragma unroll
            for (int j = 0; j < 5; ++j) {
                float4 f = hrow[j];
                s0 = fmaf(f.x, swd[4 * j],     s0);
                s1 = fmaf(f.y, swd[4 * j + 1], s1);
                s2 = fmaf(f.z, swd[4 * j + 2], s2);
                s3 = fmaf(f.w, swd[4 * j + 3], s3);
            }
            float p = (s0 + s1) + (s2 + s3);
            float a = fmaf(7.0f, p, -4.0f);     // (MAXA-MINA)*out + MINA
            spd = fmaf(0.1f, a, spd);
            pos = fmaf(0.1f, a, pos);
            outbase[(size_t)t * NVEH] = pos;
            wb[tid * RSF + 20] = (nl.x - pos) * 0.01f;
            wb[tid * RSF + 21] = spd * 0.025f;
            wb[tid * RSF + 22] = nl.y * 0.025f;
        }
        __syncthreads();
    }

    if (write_extras) {
        if (tid < VPC)
            out[(size_t)NT * NVEH + blockIdx.x * VPC + tid] = spd;
        float* hout = out + (size_t)NT * NVEH + NVEH;
        float* cout = hout + (size_t)NVEH * H;
        const float* fb = xh[NT & 1];   // h(256) lives in buf[0]
#pragma unroll
        for (int v = 0; v < VPT; ++v) {
            int gveh = blockIdx.x * VPC + vb + v;
            hout[gveh * H + u] = fb[(vb + v) * RSF + u];
            cout[gveh * H + u] = cc[v];
        }
    }
}

extern "C" void kernel_launch(void* const* d_in, const int* in_sizes, int n_in,
                              void* d_out, int out_size) {
    const float* lead_inputs = (const float*)d_in[0];
    const float* init_state  = (const float*)d_in[1];
    const float* h0          = (const float*)d_in[2];
    const float* c0          = (const float*)d_in[3];
    const float* W           = (const float*)d_in[4];
    const float* U           = (const float*)d_in[5];
    const float* b           = (const float*)d_in[6];
    const float* Wd          = (const float*)d_in[7];
    const float* bd          = (const float*)d_in[8];

    repack_kernel<<<1, 1024>>>(W, U, b, Wd, bd);
    rnncf_kernel<<<NCTA, TPC>>>(lead_inputs, init_state, h0, c0,
                                (float*)d_out, out_size);
}